// round 1
// baseline (speedup 1.0000x reference)
#include <cuda_runtime.h>
#include <cuda_bf16.h>
#include <math.h>

// Problem constants
#define NN   10000
#define EE   160000
#define ET   170000          // EE + NN self loops
#define DIN  512
#define HID  1024
#define NEG  0.2f

// ---------------------------------------------------------------------------
// Scratch (device globals; no allocation allowed)
// ---------------------------------------------------------------------------
__device__ __align__(256) float g_h   [(size_t)NN * HID];  // GAT hidden h = x@W
__device__ __align__(256) float g_lin [(size_t)NN * HID];  // residual linear
__device__ __align__(256) float g_gout[(size_t)NN * HID];  // GAT aggregation out
__device__ __align__(256) float g_x   [(size_t)NN * HID];  // activations
__device__ __align__(256) float g_als [NN * 6];
__device__ __align__(256) float g_ald [NN * 6];
__device__ __align__(256) float g_m   [NN * 6];
__device__ __align__(256) float g_s   [NN * 6];
__device__ __align__(256) float g_h3  [NN * 36];
__device__ __align__(256) float g_g3  [NN * 36];
__device__ __align__(256) float g_lin3[NN * 6];
__device__ int g_is64;

// ---------------------------------------------------------------------------
// Edge dtype detection: int64 buffers have hi-words == 0 (values < 10000)
// ---------------------------------------------------------------------------
__global__ void detect_kernel(const unsigned int* w) {
    unsigned int acc = 0;
    for (int i = 1; i < 64; i += 2) acc |= w[i];
    g_is64 = (acc == 0) ? 1 : 0;
}

__device__ __forceinline__ void edge_nodes(const void* ei, int e, int& src, int& dst) {
    if (e >= EE) { src = dst = e - EE; return; }   // self loop
    if (g_is64) {
        const long long* p = (const long long*)ei;
        src = (int)p[e]; dst = (int)p[EE + e];
    } else {
        const int* p = (const int*)ei;
        src = p[e]; dst = p[EE + e];
    }
}

__device__ __forceinline__ float atomicMaxFloat(float* addr, float value) {
    int* ia = (int*)addr;
    int old = *ia;
    while (__int_as_float(old) < value) {
        int assumed = old;
        old = atomicCAS(ia, assumed, __float_as_int(value));
        if (old == assumed) break;
    }
    return __int_as_float(old);
}

// ---------------------------------------------------------------------------
// Tiled fp32 SGEMM: C[M,Nn] = A[M,K] @ B[K,Nn], K % 8 == 0
// BM=BN=128, BK=8, 256 threads, 8x8 per-thread tile
// ---------------------------------------------------------------------------
__global__ __launch_bounds__(256)
void sgemm_kernel(const float* __restrict__ A, const float* __restrict__ B,
                  float* __restrict__ C, int M, int K, int Nn) {
    __shared__ float As[8][128];
    __shared__ float Bs[8][132];

    const int tid  = threadIdx.x;
    const int row0 = blockIdx.y * 128;
    const int col0 = blockIdx.x * 128;
    const int tx = tid & 15;      // N dir
    const int ty = tid >> 4;      // M dir

    const int arow = tid >> 1;          // 0..127
    const int acol = (tid & 1) * 4;     // 0 or 4
    const int brow = tid >> 5;          // 0..7
    const int bcol = (tid & 31) * 4;    // 0..124

    float acc[8][8];
    #pragma unroll
    for (int i = 0; i < 8; i++)
        #pragma unroll
        for (int j = 0; j < 8; j++) acc[i][j] = 0.f;

    for (int k0 = 0; k0 < K; k0 += 8) {
        // load A tile (transposed into As[k][m])
        {
            const int r = row0 + arow;
            #pragma unroll
            for (int j = 0; j < 4; j++) {
                float v = 0.f;
                if (r < M) v = A[(size_t)r * K + k0 + acol + j];
                As[acol + j][arow] = v;
            }
        }
        // load B tile
        {
            #pragma unroll
            for (int j = 0; j < 4; j++) {
                const int c = col0 + bcol + j;
                float v = 0.f;
                if (c < Nn) v = B[(size_t)(k0 + brow) * Nn + c];
                Bs[brow][bcol + j] = v;
            }
        }
        __syncthreads();

        #pragma unroll
        for (int kk = 0; kk < 8; kk++) {
            float a[8], b[8];
            #pragma unroll
            for (int i = 0; i < 8; i++) a[i] = As[kk][ty * 8 + i];
            #pragma unroll
            for (int j = 0; j < 8; j++) b[j] = Bs[kk][tx * 8 + j];
            #pragma unroll
            for (int i = 0; i < 8; i++)
                #pragma unroll
                for (int j = 0; j < 8; j++)
                    acc[i][j] += a[i] * b[j];
        }
        __syncthreads();
    }

    #pragma unroll
    for (int i = 0; i < 8; i++) {
        const int r = row0 + ty * 8 + i;
        if (r >= M) continue;
        #pragma unroll
        for (int j = 0; j < 8; j++) {
            const int c = col0 + tx * 8 + j;
            if (c < Nn) C[(size_t)r * Nn + c] = acc[i][j];
        }
    }
}

// ---------------------------------------------------------------------------
// Attention coefficients: als[n,h] = sum_c h[n,h,c]*a_src[h,c]  (ald similarly)
// ---------------------------------------------------------------------------
__global__ void attn_coeff_kernel(const float* __restrict__ h,
                                  const float* __restrict__ a_s,
                                  const float* __restrict__ a_d,
                                  float* __restrict__ als, float* __restrict__ ald,
                                  int H, int C) {
    const int idx = blockIdx.x * blockDim.x + threadIdx.x;
    if (idx >= NN * H) return;
    const int n = idx / H, hh = idx % H;
    const float* row = h + (size_t)n * H * C + (size_t)hh * C;
    const float* as = a_s + hh * C;
    const float* ad = a_d + hh * C;
    float s1 = 0.f, s2 = 0.f;
    for (int c = 0; c < C; c++) {
        const float v = row[c];
        s1 += v * as[c];
        s2 += v * ad[c];
    }
    als[idx] = s1;
    ald[idx] = s2;
}

// ---------------------------------------------------------------------------
// Init: m = -large, s = 0, gout = 0
// ---------------------------------------------------------------------------
__global__ void init_attn_kernel(float* m, float* s, int nH, float* gout, size_t gsz) {
    const size_t stride = (size_t)gridDim.x * blockDim.x;
    for (size_t i = blockIdx.x * (size_t)blockDim.x + threadIdx.x; i < gsz; i += stride) {
        gout[i] = 0.f;
        if (i < (size_t)nH) { m[i] = -3.0e38f; s[i] = 0.f; }
    }
}

// ---------------------------------------------------------------------------
// Pass 1: segment max of leaky(als[src]+ald[dst]) over dst
// ---------------------------------------------------------------------------
__global__ void edge_max_kernel(const void* __restrict__ ei,
                                const float* __restrict__ als,
                                const float* __restrict__ ald,
                                float* m, int H) {
    const int t = blockIdx.x * blockDim.x + threadIdx.x;
    if (t >= ET * H) return;
    const int e = t / H, hh = t - e * H;
    int src, dst;
    edge_nodes(ei, e, src, dst);
    float v = als[src * H + hh] + ald[dst * H + hh];
    v = v > 0.f ? v : NEG * v;
    atomicMaxFloat(&m[dst * H + hh], v);
}

// ---------------------------------------------------------------------------
// Pass 2: s[dst] += exp(e - m[dst])
// ---------------------------------------------------------------------------
__global__ void edge_sum_kernel(const void* __restrict__ ei,
                                const float* __restrict__ als,
                                const float* __restrict__ ald,
                                const float* __restrict__ m,
                                float* s, int H) {
    const int t = blockIdx.x * blockDim.x + threadIdx.x;
    if (t >= ET * H) return;
    const int e = t / H, hh = t - e * H;
    int src, dst;
    edge_nodes(ei, e, src, dst);
    float v = als[src * H + hh] + ald[dst * H + hh];
    v = v > 0.f ? v : NEG * v;
    atomicAdd(&s[dst * H + hh], __expf(v - m[dst * H + hh]));
}

// ---------------------------------------------------------------------------
// Pass 3 (H=4, C=256): gout[dst] += alpha * h[src]   (one warp per edge)
// ---------------------------------------------------------------------------
__global__ void edge_aggr_kernel(const void* __restrict__ ei,
                                 const float* __restrict__ h,
                                 const float* __restrict__ als,
                                 const float* __restrict__ ald,
                                 const float* __restrict__ m,
                                 const float* __restrict__ s,
                                 float* __restrict__ gout) {
    const int warp = (blockIdx.x * blockDim.x + threadIdx.x) >> 5;
    const int lane = threadIdx.x & 31;
    if (warp >= ET) return;
    int src, dst;
    edge_nodes(ei, warp, src, dst);
    float alpha[4];
    #pragma unroll
    for (int hh = 0; hh < 4; hh++) {
        float v = als[src * 4 + hh] + ald[dst * 4 + hh];
        v = v > 0.f ? v : NEG * v;
        alpha[hh] = __expf(v - m[dst * 4 + hh]) / (s[dst * 4 + hh] + 1e-16f);
    }
    const float4* hrow = (const float4*)(h + (size_t)src * HID);
    float4* orow = (float4*)(gout + (size_t)dst * HID);
    #pragma unroll
    for (int it = 0; it < 8; it++) {
        const int j = lane + it * 32;               // 256 float4s per row
        float4 v = hrow[j];
        const float a = alpha[j >> 6];              // head = (j*4)/256
        v.x *= a; v.y *= a; v.z *= a; v.w *= a;
        asm volatile("red.global.add.v4.f32 [%0], {%1,%2,%3,%4};"
                     :: "l"(orow + j), "f"(v.x), "f"(v.y), "f"(v.z), "f"(v.w)
                     : "memory");
    }
}

// ---------------------------------------------------------------------------
// Pass 3 for layer 3 (H=6, C=6): thread per (edge, ch36)
// ---------------------------------------------------------------------------
__global__ void edge_aggr3_kernel(const void* __restrict__ ei,
                                  const float* __restrict__ h,
                                  const float* __restrict__ als,
                                  const float* __restrict__ ald,
                                  const float* __restrict__ m,
                                  const float* __restrict__ s,
                                  float* __restrict__ gout) {
    const int t = blockIdx.x * blockDim.x + threadIdx.x;
    if (t >= ET * 36) return;
    const int e = t / 36, c = t - e * 36;
    const int hh = c / 6;
    int src, dst;
    edge_nodes(ei, e, src, dst);
    float v = als[src * 6 + hh] + ald[dst * 6 + hh];
    v = v > 0.f ? v : NEG * v;
    const float alpha = __expf(v - m[dst * 6 + hh]) / (s[dst * 6 + hh] + 1e-16f);
    atomicAdd(&gout[(size_t)dst * 36 + c], alpha * h[(size_t)src * 36 + c]);
}

// ---------------------------------------------------------------------------
// Epilogue layers 1/2: x = elu(gout + b + lin + bl)
// ---------------------------------------------------------------------------
__global__ void epilogue_kernel(const float* __restrict__ gout,
                                const float* __restrict__ b,
                                const float* __restrict__ lin,
                                const float* __restrict__ bl,
                                float* __restrict__ x) {
    const size_t i = blockIdx.x * (size_t)blockDim.x + threadIdx.x;
    if (i >= (size_t)NN * HID) return;
    const int col = (int)(i & (HID - 1));
    const float v = gout[i] + b[col] + lin[i] + bl[col];
    x[i] = v > 0.f ? v : expm1f(v);
}

// ---------------------------------------------------------------------------
// Final: mean over 6 heads + biases + residual + log_softmax over 6 classes
// ---------------------------------------------------------------------------
__global__ void final_kernel(const float* __restrict__ g3,
                             const float* __restrict__ lin3,
                             const float* __restrict__ b3,
                             const float* __restrict__ bl3,
                             float* __restrict__ out) {
    const int n = blockIdx.x * blockDim.x + threadIdx.x;
    if (n >= NN) return;
    float lg[6];
    #pragma unroll
    for (int c = 0; c < 6; c++) {
        float sum = 0.f;
        #pragma unroll
        for (int hh = 0; hh < 6; hh++) sum += g3[(size_t)n * 36 + hh * 6 + c];
        lg[c] = sum * (1.f / 6.f) + b3[c] + lin3[n * 6 + c] + bl3[c];
    }
    float mx = lg[0];
    #pragma unroll
    for (int c = 1; c < 6; c++) mx = fmaxf(mx, lg[c]);
    float se = 0.f;
    #pragma unroll
    for (int c = 0; c < 6; c++) se += expf(lg[c] - mx);
    const float lse = logf(se) + mx;
    #pragma unroll
    for (int c = 0; c < 6; c++) out[n * 6 + c] = lg[c] - lse;
}

// ---------------------------------------------------------------------------
// Host launcher
// ---------------------------------------------------------------------------
static inline dim3 gemm_grid(int M, int Nn) {
    return dim3((Nn + 127) / 128, (M + 127) / 128);
}

extern "C" void kernel_launch(void* const* d_in, const int* in_sizes, int n_in,
                              void* d_out, int out_size) {
    const float* x0  = (const float*)d_in[0];
    const void*  ei  = d_in[1];
    const float* W1  = (const float*)d_in[2];
    const float* as1 = (const float*)d_in[3];
    const float* ad1 = (const float*)d_in[4];
    const float* b1  = (const float*)d_in[5];
    const float* Wl1 = (const float*)d_in[6];
    const float* bl1 = (const float*)d_in[7];
    const float* W2  = (const float*)d_in[8];
    const float* as2 = (const float*)d_in[9];
    const float* ad2 = (const float*)d_in[10];
    const float* b2  = (const float*)d_in[11];
    const float* Wl2 = (const float*)d_in[12];
    const float* bl2 = (const float*)d_in[13];
    const float* W3  = (const float*)d_in[14];
    const float* as3 = (const float*)d_in[15];
    const float* ad3 = (const float*)d_in[16];
    const float* b3  = (const float*)d_in[17];
    const float* Wl3 = (const float*)d_in[18];
    const float* bl3 = (const float*)d_in[19];
    float* out = (float*)d_out;

    float *h, *lin, *gout, *x, *als, *ald, *m, *s, *h3, *g3, *lin3;
    cudaGetSymbolAddress((void**)&h,    g_h);
    cudaGetSymbolAddress((void**)&lin,  g_lin);
    cudaGetSymbolAddress((void**)&gout, g_gout);
    cudaGetSymbolAddress((void**)&x,    g_x);
    cudaGetSymbolAddress((void**)&als,  g_als);
    cudaGetSymbolAddress((void**)&ald,  g_ald);
    cudaGetSymbolAddress((void**)&m,    g_m);
    cudaGetSymbolAddress((void**)&s,    g_s);
    cudaGetSymbolAddress((void**)&h3,   g_h3);
    cudaGetSymbolAddress((void**)&g3,   g_g3);
    cudaGetSymbolAddress((void**)&lin3, g_lin3);

    detect_kernel<<<1, 1>>>((const unsigned int*)ei);

    const int eh4  = (ET * 4 + 255) / 256;
    const int eh6  = (ET * 6 + 255) / 256;
    const int eagg = (ET * 32 + 255) / 256;
    const int nel  = (NN * HID + 255) / 256;

    // ---------- Layer 1 ----------
    sgemm_kernel<<<gemm_grid(NN, HID), 256>>>(x0, W1,  h,   NN, DIN, HID);
    sgemm_kernel<<<gemm_grid(NN, HID), 256>>>(x0, Wl1, lin, NN, DIN, HID);
    attn_coeff_kernel<<<(NN * 4 + 255) / 256, 256>>>(h, as1, ad1, als, ald, 4, 256);
    init_attn_kernel<<<4096, 256>>>(m, s, NN * 4, gout, (size_t)NN * HID);
    edge_max_kernel<<<eh4, 256>>>(ei, als, ald, m, 4);
    edge_sum_kernel<<<eh4, 256>>>(ei, als, ald, m, s, 4);
    edge_aggr_kernel<<<eagg, 256>>>(ei, h, als, ald, m, s, gout);
    epilogue_kernel<<<nel, 256>>>(gout, b1, lin, bl1, x);

    // ---------- Layer 2 ----------
    sgemm_kernel<<<gemm_grid(NN, HID), 256>>>(x, W2,  h,   NN, HID, HID);
    sgemm_kernel<<<gemm_grid(NN, HID), 256>>>(x, Wl2, lin, NN, HID, HID);
    attn_coeff_kernel<<<(NN * 4 + 255) / 256, 256>>>(h, as2, ad2, als, ald, 4, 256);
    init_attn_kernel<<<4096, 256>>>(m, s, NN * 4, gout, (size_t)NN * HID);
    edge_max_kernel<<<eh4, 256>>>(ei, als, ald, m, 4);
    edge_sum_kernel<<<eh4, 256>>>(ei, als, ald, m, s, 4);
    edge_aggr_kernel<<<eagg, 256>>>(ei, h, als, ald, m, s, gout);
    epilogue_kernel<<<nel, 256>>>(gout, b2, lin, bl2, x);

    // ---------- Layer 3 ----------
    sgemm_kernel<<<gemm_grid(NN, 36), 256>>>(x, W3,  h3,   NN, HID, 36);
    sgemm_kernel<<<gemm_grid(NN, 6),  256>>>(x, Wl3, lin3, NN, HID, 6);
    attn_coeff_kernel<<<(NN * 6 + 255) / 256, 256>>>(h3, as3, ad3, als, ald, 6, 6);
    init_attn_kernel<<<1024, 256>>>(m, s, NN * 6, g3, (size_t)NN * 36);
    edge_max_kernel<<<eh6, 256>>>(ei, als, ald, m, 6);
    edge_sum_kernel<<<eh6, 256>>>(ei, als, ald, m, s, 6);
    edge_aggr3_kernel<<<(ET * 36 + 255) / 256, 256>>>(ei, h3, als, ald, m, s, g3);
    final_kernel<<<(NN + 255) / 256, 256>>>(g3, lin3, b3, bl3, out);
}

// round 3
// speedup vs baseline: 3.0834x; 3.0834x over previous
#include <cuda_runtime.h>
#include <cuda_bf16.h>
#include <math.h>
#include <stdint.h>

// Problem constants
#define NN   10000
#define EE   160000
#define ET   170000          // EE + NN self loops
#define DIN  512
#define HID  1024
#define NEG  0.2f

// ---------------------------------------------------------------------------
// Scratch (device globals; no allocation allowed)
// ---------------------------------------------------------------------------
__device__ __align__(256) float g_h   [(size_t)NN * HID];
__device__ __align__(256) float g_lin [(size_t)NN * HID];
__device__ __align__(256) float g_gout[(size_t)NN * HID];
__device__ __align__(256) float g_x   [(size_t)NN * HID];
__device__ __align__(256) float g_als [NN * 6];
__device__ __align__(256) float g_ald [NN * 6];
__device__ __align__(256) float g_s   [NN * 6];
__device__ __align__(256) float g_h3  [NN * 36];
__device__ __align__(256) float g_g3  [NN * 36];
__device__ __align__(256) float g_lin3[NN * 6];
__device__ __align__(256) __nv_bfloat16 g_Axh[(size_t)NN * HID];
__device__ __align__(256) __nv_bfloat16 g_Axl[(size_t)NN * HID];
__device__ __align__(256) __nv_bfloat16 g_Bth[(size_t)2048 * 1024];
__device__ __align__(256) __nv_bfloat16 g_Btl[(size_t)2048 * 1024];
__device__ int g_is64;

// ---------------------------------------------------------------------------
// PTX helpers (baseline sm_80+ features only: cp.async / ldmatrix / mma.sync)
// ---------------------------------------------------------------------------
__device__ __forceinline__ uint32_t smem_u32(const void* p) {
    uint32_t a;
    asm("{ .reg .u64 t; cvta.to.shared.u64 t, %1; cvt.u32.u64 %0, t; }" : "=r"(a) : "l"(p));
    return a;
}
__device__ __forceinline__ void cp16(uint32_t saddr, const void* g, int sz) {
    asm volatile("cp.async.ca.shared.global [%0], [%1], 16, %2;"
                 :: "r"(saddr), "l"(g), "r"(sz));
}
#define CP_COMMIT() asm volatile("cp.async.commit_group;" ::: "memory")
#define CP_WAIT1()  asm volatile("cp.async.wait_group 1;" ::: "memory")

#define LDSM4(r, addr) \
    asm volatile("ldmatrix.sync.aligned.m8n8.x4.shared.b16 {%0,%1,%2,%3}, [%4];" \
                 : "=r"((r)[0]), "=r"((r)[1]), "=r"((r)[2]), "=r"((r)[3]) : "r"(addr))

#define MMA16816(c, a, b) \
    asm volatile("mma.sync.aligned.m16n8k16.row.col.f32.bf16.bf16.f32 " \
                 "{%0,%1,%2,%3}, {%4,%5,%6,%7}, {%8,%9}, {%0,%1,%2,%3};" \
                 : "+f"((c)[0]), "+f"((c)[1]), "+f"((c)[2]), "+f"((c)[3]) \
                 : "r"((a)[0]), "r"((a)[1]), "r"((a)[2]), "r"((a)[3]), \
                   "r"((b)[0]), "r"((b)[1]))

// ---------------------------------------------------------------------------
// Edge dtype detection (int64 buffers: odd 32-bit words all zero since idx<10000)
// ---------------------------------------------------------------------------
__global__ void detect_kernel(const unsigned int* w) {
    unsigned int acc = 0;
    for (int i = 1; i < 64; i += 2) acc |= w[i];
    g_is64 = (acc == 0) ? 1 : 0;
}

__device__ __forceinline__ void edge_nodes(const void* ei, int e, int& src, int& dst) {
    if (e >= EE) { src = dst = e - EE; return; }
    if (g_is64) {
        const long long* p = (const long long*)ei;
        src = (int)p[e]; dst = (int)p[EE + e];
    } else {
        const int* p = (const int*)ei;
        src = p[e]; dst = p[EE + e];
    }
}

// ---------------------------------------------------------------------------
// fp32 -> bf16 hi/lo split (vectorized by 4)
// ---------------------------------------------------------------------------
__global__ void convA_kernel(const float* __restrict__ x,
                             __nv_bfloat16* __restrict__ hi,
                             __nv_bfloat16* __restrict__ lo, int n4) {
    const int i = blockIdx.x * blockDim.x + threadIdx.x;
    if (i >= n4) return;
    const float4 v = ((const float4*)x)[i];
    __nv_bfloat16 h[4], l[4];
    const float vv[4] = {v.x, v.y, v.z, v.w};
    #pragma unroll
    for (int j = 0; j < 4; j++) {
        h[j] = __float2bfloat16(vv[j]);
        l[j] = __float2bfloat16(vv[j] - __bfloat162float(h[j]));
    }
    *(uint2*)(hi + (size_t)i * 4) = *(uint2*)h;
    *(uint2*)(lo + (size_t)i * 4) = *(uint2*)l;
}

// ---------------------------------------------------------------------------
// W [K][Nw] fp32 -> Bt [rowoff+Nw][ldout] bf16 hi/lo (transposed)
// ---------------------------------------------------------------------------
__global__ void convB_kernel(const float* __restrict__ W, int K, int Nw,
                             __nv_bfloat16* __restrict__ outh,
                             __nv_bfloat16* __restrict__ outl,
                             int rowoff, int ldout) {
    __shared__ float t[32][33];
    const int n0 = blockIdx.x * 32, k0 = blockIdx.y * 32;
    const int tx = threadIdx.x, ty = threadIdx.y;
    #pragma unroll
    for (int j = 0; j < 4; j++) {
        const int k = k0 + ty + j * 8, n = n0 + tx;
        if (k < K && n < Nw) t[ty + j * 8][tx] = W[(size_t)k * Nw + n];
    }
    __syncthreads();
    #pragma unroll
    for (int j = 0; j < 4; j++) {
        const int n = n0 + ty + j * 8, k = k0 + tx;
        if (n < Nw && k < K) {
            const float v = t[tx][ty + j * 8];
            const __nv_bfloat16 h = __float2bfloat16(v);
            outh[(size_t)(rowoff + n) * ldout + k] = h;
            outl[(size_t)(rowoff + n) * ldout + k] = __float2bfloat16(v - __bfloat162float(h));
        }
    }
}

__global__ void zero_bf16_kernel(__nv_bfloat16* a, __nv_bfloat16* b, int n) {
    const int i = blockIdx.x * blockDim.x + threadIdx.x;
    if (i < n) { a[i] = __float2bfloat16(0.f); b[i] = __float2bfloat16(0.f); }
}

// ---------------------------------------------------------------------------
// HMMA split-bf16 GEMM: C[M,*] = A[M,K] @ Bt[*,K]^T with fp32-level accuracy
// via C = Ah*Bh + Ah*Bl + Al*Bh. Block tile 128x128, 8 warps (64x32 each),
// K-stage 32, double-buffered cp.async. SMEM rows = [hi 32bf16 | lo 32bf16]
// = 128B, 16B-chunk XOR swizzle -> conflict-free ldmatrix.
// Epilogue routes column n: n<split -> out0, split<=n<nvalid -> out1.
// ---------------------------------------------------------------------------
__global__ __launch_bounds__(256)
void hmma_gemm_kernel(const __nv_bfloat16* __restrict__ Ahg,
                      const __nv_bfloat16* __restrict__ Alg,
                      const __nv_bfloat16* __restrict__ Bhg,
                      const __nv_bfloat16* __restrict__ Blg,
                      int M, int K,
                      float* __restrict__ out0, int ld0, int split,
                      float* __restrict__ out1, int ld1, int nvalid) {
    extern __shared__ char smem[];
    constexpr int STG = 32768;      // 16KB A + 16KB B per stage
    const int tid = threadIdx.x;
    const int lane = tid & 31, wid = tid >> 5;
    const int wm = wid >> 2, wn = wid & 3;          // 2 x 4 warp grid
    const int m0 = blockIdx.y * 128, n0 = blockIdx.x * 128;
    const uint32_t sbase = smem_u32(smem);

    float acc[4][4][4];
    #pragma unroll
    for (int i = 0; i < 4; i++)
        #pragma unroll
        for (int j = 0; j < 4; j++)
            #pragma unroll
            for (int k = 0; k < 4; k++) acc[i][j][k] = 0.f;

    // per-lane ldmatrix geometry
    const int g = lane >> 3, lr = lane & 7;
    const int xr = ((g & 1) << 3) + lr;             // row within 16-row tile
    const int cbase = g >> 1;                       // chunk half (k 0-7 vs 8-15)
    const int swz = xr & 7;
    uint32_t aoff[4], boff[2];
    #pragma unroll
    for (int mt = 0; mt < 4; mt++) aoff[mt] = (uint32_t)((wm * 64 + mt * 16 + xr) * 128);
    #pragma unroll
    for (int np = 0; np < 2; np++) boff[np] = (uint32_t)((wn * 32 + np * 16 + xr) * 128);

    const int nch = K >> 5;   // stages of 32

    // stage loader: 8 chunks of 16B per row; chunks 0-3 = hi, 4-7 = lo
    auto LOADSTAGE = [&](int buf, int k0) {
        const uint32_t sA = sbase + buf * STG;
        const uint32_t sB = sA + 16384;
        #pragma unroll
        for (int i = 0; i < 4; i++) {
            const int ch = tid + i * 256;           // 0..1023
            const int row = ch >> 3, c = ch & 7;
            const int m = m0 + row;
            const int mm = (m < M) ? m : 0;
            const __nv_bfloat16* srcA = (c < 4)
                ? Ahg + (size_t)mm * K + k0 + c * 8
                : Alg + (size_t)mm * K + k0 + (c - 4) * 8;
            cp16(sA + row * 128 + ((c ^ (row & 7)) << 4), srcA, (m < M) ? 16 : 0);
            const int n = n0 + row;
            const __nv_bfloat16* srcB = (c < 4)
                ? Bhg + (size_t)n * K + k0 + c * 8
                : Blg + (size_t)n * K + k0 + (c - 4) * 8;
            cp16(sB + row * 128 + ((c ^ (row & 7)) << 4), srcB, 16);
        }
    };

    LOADSTAGE(0, 0);
    CP_COMMIT();

    for (int ci = 0; ci < nch; ci++) {
        if (ci + 1 < nch) LOADSTAGE((ci + 1) & 1, (ci + 1) * 32);
        CP_COMMIT();
        CP_WAIT1();
        __syncthreads();

        const uint32_t sA = sbase + (ci & 1) * STG;
        const uint32_t sB = sA + 16384;
        #pragma unroll
        for (int ks = 0; ks < 2; ks++) {
            const int ch = ks * 2 + cbase;
            uint32_t ah[4][4], al[4][4], bh[4][2], bl[4][2];
            #pragma unroll
            for (int mt = 0; mt < 4; mt++) {
                LDSM4(ah[mt], sA + aoff[mt] + ((ch ^ swz) << 4));
                LDSM4(al[mt], sA + aoff[mt] + (((ch + 4) ^ swz) << 4));
            }
            #pragma unroll
            for (int np = 0; np < 2; np++) {
                uint32_t r[4];
                LDSM4(r, sB + boff[np] + ((ch ^ swz) << 4));
                bh[2 * np][0] = r[0]; bh[2 * np + 1][0] = r[1];
                bh[2 * np][1] = r[2]; bh[2 * np + 1][1] = r[3];
                LDSM4(r, sB + boff[np] + (((ch + 4) ^ swz) << 4));
                bl[2 * np][0] = r[0]; bl[2 * np + 1][0] = r[1];
                bl[2 * np][1] = r[2]; bl[2 * np + 1][1] = r[3];
            }
            #pragma unroll
            for (int mt = 0; mt < 4; mt++)
                #pragma unroll
                for (int nt = 0; nt < 4; nt++) {
                    MMA16816(acc[mt][nt], ah[mt], bh[nt]);
                    MMA16816(acc[mt][nt], ah[mt], bl[nt]);
                    MMA16816(acc[mt][nt], al[mt], bh[nt]);
                }
        }
        __syncthreads();
    }

    // epilogue
    const int mrow = lane >> 2, ncol = (lane & 3) << 1;
    #pragma unroll
    for (int mt = 0; mt < 4; mt++) {
        #pragma unroll
        for (int nt = 0; nt < 4; nt++) {
            const int n = n0 + wn * 32 + nt * 8 + ncol;
            if (n >= nvalid) continue;
            float* base;
            int nn;
            if (n < split) { base = out0; nn = n;         }
            else           { base = out1; nn = n - split; }
            const int ld = (n < split) ? ld0 : ld1;
            const int m1 = m0 + wm * 64 + mt * 16 + mrow;
            if (m1 < M)
                *(float2*)(base + (size_t)m1 * ld + nn) =
                    make_float2(acc[mt][nt][0], acc[mt][nt][1]);
            const int m2 = m1 + 8;
            if (m2 < M)
                *(float2*)(base + (size_t)m2 * ld + nn) =
                    make_float2(acc[mt][nt][2], acc[mt][nt][3]);
        }
    }
}

// ---------------------------------------------------------------------------
// Attention coefficients, warp per (n,head), C=256, H=4
// ---------------------------------------------------------------------------
__global__ void attn_warp_kernel(const float* __restrict__ h,
                                 const float* __restrict__ a_s,
                                 const float* __restrict__ a_d,
                                 float* __restrict__ als, float* __restrict__ ald) {
    const int w = (blockIdx.x * blockDim.x + threadIdx.x) >> 5;
    if (w >= NN * 4) return;
    const int lane = threadIdx.x & 31;
    const int hh = w & 3;
    const float4* row = (const float4*)(h + (size_t)w * 256);
    const float4* as = (const float4*)(a_s + hh * 256);
    const float4* ad = (const float4*)(a_d + hh * 256);
    float s1 = 0.f, s2 = 0.f;
    #pragma unroll
    for (int i = 0; i < 2; i++) {
        const float4 v = row[lane + i * 32];
        const float4 a = as[lane + i * 32];
        const float4 b = ad[lane + i * 32];
        s1 += v.x * a.x + v.y * a.y + v.z * a.z + v.w * a.w;
        s2 += v.x * b.x + v.y * b.y + v.z * b.z + v.w * b.w;
    }
    #pragma unroll
    for (int o = 16; o; o >>= 1) {
        s1 += __shfl_xor_sync(0xffffffffu, s1, o);
        s2 += __shfl_xor_sync(0xffffffffu, s2, o);
    }
    if (lane == 0) { als[w] = s1; ald[w] = s2; }
}

// Generic small version (layer 3: H=6, C=6)
__global__ void attn_coeff_kernel(const float* __restrict__ h,
                                  const float* __restrict__ a_s,
                                  const float* __restrict__ a_d,
                                  float* __restrict__ als, float* __restrict__ ald,
                                  int H, int C) {
    const int idx = blockIdx.x * blockDim.x + threadIdx.x;
    if (idx >= NN * H) return;
    const int hh = idx % H;
    const float* row = h + (size_t)idx * C;
    const float* as = a_s + hh * C;
    const float* ad = a_d + hh * C;
    float s1 = 0.f, s2 = 0.f;
    for (int c = 0; c < C; c++) {
        const float v = row[c];
        s1 += v * as[c];
        s2 += v * ad[c];
    }
    als[idx] = s1;
    ald[idx] = s2;
}

// ---------------------------------------------------------------------------
// Init: s = 0, gout = 0   (no max pass: softmax is shift-invariant, logits O(1))
// ---------------------------------------------------------------------------
__global__ void init_attn_kernel(float* s, int nH, float* gout, size_t gsz) {
    const size_t stride = (size_t)gridDim.x * blockDim.x;
    for (size_t i = blockIdx.x * (size_t)blockDim.x + threadIdx.x; i < gsz; i += stride) {
        gout[i] = 0.f;
        if (i < (size_t)nH) s[i] = 0.f;
    }
}

// ---------------------------------------------------------------------------
// Pass 1: s[dst] += exp(leaky(als[src]+ald[dst]))
// ---------------------------------------------------------------------------
__global__ void edge_sum_kernel(const void* __restrict__ ei,
                                const float* __restrict__ als,
                                const float* __restrict__ ald,
                                float* s, int H) {
    const int t = blockIdx.x * blockDim.x + threadIdx.x;
    if (t >= ET * H) return;
    const int e = t / H, hh = t - e * H;
    int src, dst;
    edge_nodes(ei, e, src, dst);
    float v = als[src * H + hh] + ald[dst * H + hh];
    v = v > 0.f ? v : NEG * v;
    atomicAdd(&s[dst * H + hh], __expf(v));
}

// ---------------------------------------------------------------------------
// Pass 2 (H=4, C=256): gout[dst] += alpha * h[src], warp per edge, red.v4
// ---------------------------------------------------------------------------
__global__ void edge_aggr_kernel(const void* __restrict__ ei,
                                 const float* __restrict__ h,
                                 const float* __restrict__ als,
                                 const float* __restrict__ ald,
                                 const float* __restrict__ s,
                                 float* __restrict__ gout) {
    const int warp = (blockIdx.x * blockDim.x + threadIdx.x) >> 5;
    const int lane = threadIdx.x & 31;
    if (warp >= ET) return;
    int src, dst;
    edge_nodes(ei, warp, src, dst);
    float alpha[4];
    #pragma unroll
    for (int hh = 0; hh < 4; hh++) {
        float v = als[src * 4 + hh] + ald[dst * 4 + hh];
        v = v > 0.f ? v : NEG * v;
        alpha[hh] = __expf(v) / (s[dst * 4 + hh] + 1e-16f);
    }
    const float4* hrow = (const float4*)(h + (size_t)src * HID);
    float4* orow = (float4*)(gout + (size_t)dst * HID);
    #pragma unroll
    for (int it = 0; it < 8; it++) {
        const int j = lane + it * 32;
        float4 v = hrow[j];
        const float a = alpha[j >> 6];
        v.x *= a; v.y *= a; v.z *= a; v.w *= a;
        asm volatile("red.global.add.v4.f32 [%0], {%1,%2,%3,%4};"
                     :: "l"(orow + j), "f"(v.x), "f"(v.y), "f"(v.z), "f"(v.w)
                     : "memory");
    }
}

// Pass 2 for layer 3 (H=6, C=6)
__global__ void edge_aggr3_kernel(const void* __restrict__ ei,
                                  const float* __restrict__ h,
                                  const float* __restrict__ als,
                                  const float* __restrict__ ald,
                                  const float* __restrict__ s,
                                  float* __restrict__ gout) {
    const int t = blockIdx.x * blockDim.x + threadIdx.x;
    if (t >= ET * 36) return;
    const int e = t / 36, c = t - e * 36;
    const int hh = c / 6;
    int src, dst;
    edge_nodes(ei, e, src, dst);
    float v = als[src * 6 + hh] + ald[dst * 6 + hh];
    v = v > 0.f ? v : NEG * v;
    const float alpha = __expf(v) / (s[dst * 6 + hh] + 1e-16f);
    atomicAdd(&gout[(size_t)dst * 36 + c], alpha * h[(size_t)src * 36 + c]);
}

// ---------------------------------------------------------------------------
// Epilogue layers 1/2: x = elu(gout + b + lin + bl)
// ---------------------------------------------------------------------------
__global__ void epilogue_kernel(const float* __restrict__ gout,
                                const float* __restrict__ b,
                                const float* __restrict__ lin,
                                const float* __restrict__ bl,
                                float* __restrict__ x) {
    const size_t i = blockIdx.x * (size_t)blockDim.x + threadIdx.x;
    if (i >= (size_t)NN * HID) return;
    const int col = (int)(i & (HID - 1));
    const float v = gout[i] + b[col] + lin[i] + bl[col];
    x[i] = v > 0.f ? v : expm1f(v);
}

// ---------------------------------------------------------------------------
// Final: mean over heads + biases + residual + log_softmax
// ---------------------------------------------------------------------------
__global__ void final_kernel(const float* __restrict__ g3,
                             const float* __restrict__ lin3,
                             const float* __restrict__ b3,
                             const float* __restrict__ bl3,
                             float* __restrict__ out) {
    const int n = blockIdx.x * blockDim.x + threadIdx.x;
    if (n >= NN) return;
    float lg[6];
    #pragma unroll
    for (int c = 0; c < 6; c++) {
        float sum = 0.f;
        #pragma unroll
        for (int hh = 0; hh < 6; hh++) sum += g3[(size_t)n * 36 + hh * 6 + c];
        lg[c] = sum * (1.f / 6.f) + b3[c] + lin3[n * 6 + c] + bl3[c];
    }
    float mx = lg[0];
    #pragma unroll
    for (int c = 1; c < 6; c++) mx = fmaxf(mx, lg[c]);
    float se = 0.f;
    #pragma unroll
    for (int c = 0; c < 6; c++) se += expf(lg[c] - mx);
    const float lse = logf(se) + mx;
    #pragma unroll
    for (int c = 0; c < 6; c++) out[n * 6 + c] = lg[c] - lse;
}

// ---------------------------------------------------------------------------
// Host launcher
// ---------------------------------------------------------------------------
extern "C" void kernel_launch(void* const* d_in, const int* in_sizes, int n_in,
                              void* d_out, int out_size) {
    const float* x0  = (const float*)d_in[0];
    const void*  ei  = d_in[1];
    const float* W1  = (const float*)d_in[2];
    const float* as1 = (const float*)d_in[3];
    const float* ad1 = (const float*)d_in[4];
    const float* b1  = (const float*)d_in[5];
    const float* Wl1 = (const float*)d_in[6];
    const float* bl1 = (const float*)d_in[7];
    const float* W2  = (const float*)d_in[8];
    const float* as2 = (const float*)d_in[9];
    const float* ad2 = (const float*)d_in[10];
    const float* b2  = (const float*)d_in[11];
    const float* Wl2 = (const float*)d_in[12];
    const float* bl2 = (const float*)d_in[13];
    const float* W3  = (const float*)d_in[14];
    const float* as3 = (const float*)d_in[15];
    const float* ad3 = (const float*)d_in[16];
    const float* b3  = (const float*)d_in[17];
    const float* Wl3 = (const float*)d_in[18];
    const float* bl3 = (const float*)d_in[19];
    float* out = (float*)d_out;

    float *h, *lin, *gout, *x, *als, *ald, *s, *h3, *g3, *lin3;
    __nv_bfloat16 *Axh, *Axl, *Bth, *Btl;
    cudaGetSymbolAddress((void**)&h,    g_h);
    cudaGetSymbolAddress((void**)&lin,  g_lin);
    cudaGetSymbolAddress((void**)&gout, g_gout);
    cudaGetSymbolAddress((void**)&x,    g_x);
    cudaGetSymbolAddress((void**)&als,  g_als);
    cudaGetSymbolAddress((void**)&ald,  g_ald);
    cudaGetSymbolAddress((void**)&s,    g_s);
    cudaGetSymbolAddress((void**)&h3,   g_h3);
    cudaGetSymbolAddress((void**)&g3,   g_g3);
    cudaGetSymbolAddress((void**)&lin3, g_lin3);
    cudaGetSymbolAddress((void**)&Axh,  g_Axh);
    cudaGetSymbolAddress((void**)&Axl,  g_Axl);
    cudaGetSymbolAddress((void**)&Bth,  g_Bth);
    cudaGetSymbolAddress((void**)&Btl,  g_Btl);

    const int SMEMB = 65536;   // 2 stages x 32KB
    cudaFuncSetAttribute(hmma_gemm_kernel,
                         cudaFuncAttributeMaxDynamicSharedMemorySize, SMEMB);

    detect_kernel<<<1, 1>>>((const unsigned int*)ei);

    const int eh4  = (ET * 4 + 255) / 256;
    const int eh6  = (ET * 6 + 255) / 256;
    const int eagg = (ET * 32 + 255) / 256;
    const int nel  = (NN * HID + 255) / 256;
    const dim3 cbT(32, 8);

    // ---------------- Layer 1 (K=512, N = 1024 | 1024 fused) ----------------
    convB_kernel<<<dim3(32, 16), cbT>>>(W1,  512, 1024, Bth, Btl, 0,    512);
    convB_kernel<<<dim3(32, 16), cbT>>>(Wl1, 512, 1024, Bth, Btl, 1024, 512);
    convA_kernel<<<(NN * 512 / 4 + 255) / 256, 256>>>(x0, Axh, Axl, NN * 512 / 4);
    hmma_gemm_kernel<<<dim3(16, 79), 256, SMEMB>>>(Axh, Axl, Bth, Btl,
        NN, 512, h, 1024, 1024, lin, 1024, 2048);
    attn_warp_kernel<<<(NN * 4 * 32 + 255) / 256, 256>>>(h, as1, ad1, als, ald);
    init_attn_kernel<<<4096, 256>>>(s, NN * 4, gout, (size_t)NN * HID);
    edge_sum_kernel<<<eh4, 256>>>(ei, als, ald, s, 4);
    edge_aggr_kernel<<<eagg, 256>>>(ei, h, als, ald, s, gout);
    epilogue_kernel<<<nel, 256>>>(gout, b1, lin, bl1, x);

    // ---------------- Layer 2 (K=1024) ----------------
    convB_kernel<<<dim3(32, 32), cbT>>>(W2,  1024, 1024, Bth, Btl, 0,    1024);
    convB_kernel<<<dim3(32, 32), cbT>>>(Wl2, 1024, 1024, Bth, Btl, 1024, 1024);
    convA_kernel<<<(NN * 1024 / 4 + 255) / 256, 256>>>(x, Axh, Axl, NN * 1024 / 4);
    hmma_gemm_kernel<<<dim3(16, 79), 256, SMEMB>>>(Axh, Axl, Bth, Btl,
        NN, 1024, h, 1024, 1024, lin, 1024, 2048);
    attn_warp_kernel<<<(NN * 4 * 32 + 255) / 256, 256>>>(h, as2, ad2, als, ald);
    init_attn_kernel<<<4096, 256>>>(s, NN * 4, gout, (size_t)NN * HID);
    edge_sum_kernel<<<eh4, 256>>>(ei, als, ald, s, 4);
    edge_aggr_kernel<<<eagg, 256>>>(ei, h, als, ald, s, gout);
    epilogue_kernel<<<nel, 256>>>(gout, b2, lin, bl2, x);

    // ---------------- Layer 3 (K=1024, N tile = 128 zero-padded) ----------------
    zero_bf16_kernel<<<(128 * 1024 + 255) / 256, 256>>>(Bth, Btl, 128 * 1024);
    convB_kernel<<<dim3(2, 32), cbT>>>(W3,  1024, 36, Bth, Btl, 0,  1024);
    convB_kernel<<<dim3(1, 32), cbT>>>(Wl3, 1024, 6,  Bth, Btl, 36, 1024);
    convA_kernel<<<(NN * 1024 / 4 + 255) / 256, 256>>>(x, Axh, Axl, NN * 1024 / 4);
    hmma_gemm_kernel<<<dim3(1, 79), 256, SMEMB>>>(Axh, Axl, Bth, Btl,
        NN, 1024, h3, 36, 36, lin3, 6, 42);
    attn_coeff_kernel<<<(NN * 6 + 255) / 256, 256>>>(h3, as3, ad3, als, ald, 6, 6);
    init_attn_kernel<<<1024, 256>>>(s, NN * 6, g3, (size_t)NN * 36);
    edge_sum_kernel<<<eh6, 256>>>(ei, als, ald, s, 6);
    edge_aggr3_kernel<<<(ET * 36 + 255) / 256, 256>>>(ei, h3, als, ald, s, g3);
    final_kernel<<<(NN + 255) / 256, 256>>>(g3, lin3, b3, bl3, out);
}

// round 4
// speedup vs baseline: 3.6668x; 1.1892x over previous
#include <cuda_runtime.h>
#include <cuda_bf16.h>
#include <math.h>
#include <stdint.h>

// Problem constants
#define NN   10000
#define EE   160000
#define ET   170000          // EE + NN self loops
#define DIN  512
#define HID  1024
#define NEG  0.2f
#define DCAP 512             // cached edges per dst (layers 1-2)
#define DCAP3 256            // cached edges per dst (layer 3)

// ---------------------------------------------------------------------------
// Scratch (device globals; no allocation allowed)
// ---------------------------------------------------------------------------
__device__ __align__(256) float g_h   [(size_t)NN * HID];
__device__ __align__(256) float g_lin [(size_t)NN * HID];
__device__ __align__(256) float g_als [NN * 6];
__device__ __align__(256) float g_ald [NN * 6];
__device__ __align__(256) float g_h3  [NN * 36];
__device__ __align__(256) float g_lin3[NN * 6];
__device__ __align__(256) __nv_bfloat16 g_Axh[(size_t)NN * HID];
__device__ __align__(256) __nv_bfloat16 g_Axl[(size_t)NN * HID];
__device__ __align__(256) __nv_bfloat16 g_Bth[(size_t)2048 * 1024];
__device__ __align__(256) __nv_bfloat16 g_Btl[(size_t)2048 * 1024];
__device__ __align__(256) int g_deg [NN];
__device__ __align__(256) int g_cnt [NN];
__device__ __align__(256) int g_rowptr[NN + 1];
__device__ __align__(256) int g_csr [ET];
__device__ int g_is64;

// ---------------------------------------------------------------------------
// PTX helpers (baseline sm_80+ features: cp.async / ldmatrix / mma.sync)
// ---------------------------------------------------------------------------
__device__ __forceinline__ uint32_t smem_u32(const void* p) {
    uint32_t a;
    asm("{ .reg .u64 t; cvta.to.shared.u64 t, %1; cvt.u32.u64 %0, t; }" : "=r"(a) : "l"(p));
    return a;
}
__device__ __forceinline__ void cp16(uint32_t saddr, const void* g, int sz) {
    asm volatile("cp.async.ca.shared.global [%0], [%1], 16, %2;"
                 :: "r"(saddr), "l"(g), "r"(sz));
}
#define CP_COMMIT() asm volatile("cp.async.commit_group;" ::: "memory")
#define CP_WAIT2()  asm volatile("cp.async.wait_group 2;" ::: "memory")

#define LDSM4(r, addr) \
    asm volatile("ldmatrix.sync.aligned.m8n8.x4.shared.b16 {%0,%1,%2,%3}, [%4];" \
                 : "=r"((r)[0]), "=r"((r)[1]), "=r"((r)[2]), "=r"((r)[3]) : "r"(addr))

#define MMA16816(c, a, b) \
    asm volatile("mma.sync.aligned.m16n8k16.row.col.f32.bf16.bf16.f32 " \
                 "{%0,%1,%2,%3}, {%4,%5,%6,%7}, {%8,%9}, {%0,%1,%2,%3};" \
                 : "+f"((c)[0]), "+f"((c)[1]), "+f"((c)[2]), "+f"((c)[3]) \
                 : "r"((a)[0]), "r"((a)[1]), "r"((a)[2]), "r"((a)[3]), \
                   "r"((b)[0]), "r"((b)[1]))

// ---------------------------------------------------------------------------
// Edge dtype detection (int64 buffers: odd 32-bit words zero since idx<10000)
// ---------------------------------------------------------------------------
__global__ void detect_kernel(const unsigned int* w) {
    unsigned int acc = 0;
    for (int i = 1; i < 64; i += 2) acc |= w[i];
    g_is64 = (acc == 0) ? 1 : 0;
}

__device__ __forceinline__ void edge_nodes(const void* ei, int e, int& src, int& dst) {
    if (e >= EE) { src = dst = e - EE; return; }
    if (g_is64) {
        const long long* p = (const long long*)ei;
        src = (int)p[e]; dst = (int)p[EE + e];
    } else {
        const int* p = (const int*)ei;
        src = p[e]; dst = p[EE + e];
    }
}

// ---------------------------------------------------------------------------
// CSR build
// ---------------------------------------------------------------------------
__global__ void zero_csr_kernel(int* deg, int* cnt) {
    const int i = blockIdx.x * blockDim.x + threadIdx.x;
    if (i < NN) { deg[i] = 0; cnt[i] = 0; }
}
__global__ void count_kernel(const void* __restrict__ ei, int* deg) {
    const int e = blockIdx.x * blockDim.x + threadIdx.x;
    if (e >= ET) return;
    int src, dst;
    edge_nodes(ei, e, src, dst);
    atomicAdd(&deg[dst], 1);
}
__global__ void scan_kernel(const int* __restrict__ deg, int* rowptr) {
    __shared__ int sm[1024];
    __shared__ int carry;
    if (threadIdx.x == 0) carry = 0;
    __syncthreads();
    for (int base = 0; base < NN; base += 1024) {
        const int i = base + threadIdx.x;
        const int v = (i < NN) ? deg[i] : 0;
        sm[threadIdx.x] = v;
        __syncthreads();
        for (int off = 1; off < 1024; off <<= 1) {
            const int t = (threadIdx.x >= off) ? sm[threadIdx.x - off] : 0;
            __syncthreads();
            sm[threadIdx.x] += t;
            __syncthreads();
        }
        if (i < NN) rowptr[i] = carry + sm[threadIdx.x] - v;
        __syncthreads();
        if (threadIdx.x == 0) carry += sm[1023];
        __syncthreads();
    }
    if (threadIdx.x == 0) rowptr[NN] = carry;
}
__global__ void scatter_kernel(const void* __restrict__ ei,
                               const int* __restrict__ rowptr, int* cnt, int* csr) {
    const int e = blockIdx.x * blockDim.x + threadIdx.x;
    if (e >= ET) return;
    int src, dst;
    edge_nodes(ei, e, src, dst);
    const int pos = rowptr[dst] + atomicAdd(&cnt[dst], 1);
    csr[pos] = src;
}

// ---------------------------------------------------------------------------
// fp32 -> bf16 hi/lo split (only for the primary input x0)
// ---------------------------------------------------------------------------
__global__ void convA_kernel(const float* __restrict__ x,
                             __nv_bfloat16* __restrict__ hi,
                             __nv_bfloat16* __restrict__ lo, int n4) {
    const int i = blockIdx.x * blockDim.x + threadIdx.x;
    if (i >= n4) return;
    const float4 v = ((const float4*)x)[i];
    __nv_bfloat16 h[4], l[4];
    const float vv[4] = {v.x, v.y, v.z, v.w};
    #pragma unroll
    for (int j = 0; j < 4; j++) {
        h[j] = __float2bfloat16(vv[j]);
        l[j] = __float2bfloat16(vv[j] - __bfloat162float(h[j]));
    }
    *(uint2*)(hi + (size_t)i * 4) = *(uint2*)h;
    *(uint2*)(lo + (size_t)i * 4) = *(uint2*)l;
}

// ---------------------------------------------------------------------------
// W [K][Nw] fp32 -> Bt [rowoff+Nw][ldout] bf16 hi/lo (transposed)
// ---------------------------------------------------------------------------
__global__ void convB_kernel(const float* __restrict__ W, int K, int Nw,
                             __nv_bfloat16* __restrict__ outh,
                             __nv_bfloat16* __restrict__ outl,
                             int rowoff, int ldout) {
    __shared__ float t[32][33];
    const int n0 = blockIdx.x * 32, k0 = blockIdx.y * 32;
    const int tx = threadIdx.x, ty = threadIdx.y;
    #pragma unroll
    for (int j = 0; j < 4; j++) {
        const int k = k0 + ty + j * 8, n = n0 + tx;
        if (k < K && n < Nw) t[ty + j * 8][tx] = W[(size_t)k * Nw + n];
    }
    __syncthreads();
    #pragma unroll
    for (int j = 0; j < 4; j++) {
        const int n = n0 + ty + j * 8, k = k0 + tx;
        if (n < Nw && k < K) {
            const float v = t[tx][ty + j * 8];
            const __nv_bfloat16 h = __float2bfloat16(v);
            outh[(size_t)(rowoff + n) * ldout + k] = h;
            outl[(size_t)(rowoff + n) * ldout + k] = __float2bfloat16(v - __bfloat162float(h));
        }
    }
}

__global__ void zero_bf16_kernel(__nv_bfloat16* a, __nv_bfloat16* b, int n) {
    const int i = blockIdx.x * blockDim.x + threadIdx.x;
    if (i < n) { a[i] = __float2bfloat16(0.f); b[i] = __float2bfloat16(0.f); }
}
__global__ void zero_f32_kernel(float* a, int na, float* b, int nb) {
    const int i = blockIdx.x * blockDim.x + threadIdx.x;
    if (i < na) a[i] = 0.f;
    if (i < nb) b[i] = 0.f;
}

// ---------------------------------------------------------------------------
// HMMA split-bf16 GEMM: C = Ah*Bh + Ah*Bl + Al*Bh (fp32 accuracy)
// 128x128 tile, 8 warps (64x32), 3-stage cp.async pipeline, K-stage 32.
// gridDim.z>1 -> split-K with red.global.add epilogue (outputs pre-zeroed).
// Column routing: n<split -> out0, else out1.
// ---------------------------------------------------------------------------
__global__ __launch_bounds__(256)
void hmma_gemm_kernel(const __nv_bfloat16* __restrict__ Ahg,
                      const __nv_bfloat16* __restrict__ Alg,
                      const __nv_bfloat16* __restrict__ Bhg,
                      const __nv_bfloat16* __restrict__ Blg,
                      int M, int K,
                      float* __restrict__ out0, int ld0, int split,
                      float* __restrict__ out1, int ld1, int nvalid) {
    extern __shared__ char smem[];
    constexpr int STG = 32768;      // 16KB A + 16KB B per stage
    const int tid = threadIdx.x;
    const int lane = tid & 31, wid = tid >> 5;
    const int wm = wid >> 2, wn = wid & 3;
    const int m0 = blockIdx.y * 128, n0 = blockIdx.x * 128;
    const uint32_t sbase = smem_u32(smem);

    const int kpn = K / gridDim.z;
    const int kbase = blockIdx.z * kpn;
    const int nch = kpn >> 5;

    float acc[4][4][4];
    #pragma unroll
    for (int i = 0; i < 4; i++)
        #pragma unroll
        for (int j = 0; j < 4; j++)
            #pragma unroll
            for (int k = 0; k < 4; k++) acc[i][j][k] = 0.f;

    const int g = lane >> 3, lr = lane & 7;
    const int xr = ((g & 1) << 3) + lr;
    const int cbase = g >> 1;
    const int swz = xr & 7;
    uint32_t aoff[4], boff[2];
    #pragma unroll
    for (int mt = 0; mt < 4; mt++) aoff[mt] = (uint32_t)((wm * 64 + mt * 16 + xr) * 128);
    #pragma unroll
    for (int np = 0; np < 2; np++) boff[np] = (uint32_t)((wn * 32 + np * 16 + xr) * 128);

    auto LOADSTAGE = [&](int buf, int k0) {
        const uint32_t sA = sbase + buf * STG;
        const uint32_t sB = sA + 16384;
        #pragma unroll
        for (int i = 0; i < 4; i++) {
            const int ch = tid + i * 256;
            const int row = ch >> 3, c = ch & 7;
            const int m = m0 + row;
            const int mm = (m < M) ? m : 0;
            const __nv_bfloat16* srcA = (c < 4)
                ? Ahg + (size_t)mm * K + k0 + c * 8
                : Alg + (size_t)mm * K + k0 + (c - 4) * 8;
            cp16(sA + row * 128 + ((c ^ (row & 7)) << 4), srcA, (m < M) ? 16 : 0);
            const int n = n0 + row;
            const __nv_bfloat16* srcB = (c < 4)
                ? Bhg + (size_t)n * K + k0 + c * 8
                : Blg + (size_t)n * K + k0 + (c - 4) * 8;
            cp16(sB + row * 128 + ((c ^ (row & 7)) << 4), srcB, 16);
        }
    };

    LOADSTAGE(0, kbase);
    CP_COMMIT();
    if (nch > 1) LOADSTAGE(1, kbase + 32);
    CP_COMMIT();

    for (int ci = 0; ci < nch; ci++) {
        if (ci + 2 < nch) LOADSTAGE((ci + 2) % 3, kbase + (ci + 2) * 32);
        CP_COMMIT();
        CP_WAIT2();
        __syncthreads();

        const uint32_t sA = sbase + (ci % 3) * STG;
        const uint32_t sB = sA + 16384;
        #pragma unroll
        for (int ks = 0; ks < 2; ks++) {
            const int ch = ks * 2 + cbase;
            uint32_t ah[4][4], al[4][4], bh[4][2], bl[4][2];
            #pragma unroll
            for (int mt = 0; mt < 4; mt++) {
                LDSM4(ah[mt], sA + aoff[mt] + ((ch ^ swz) << 4));
                LDSM4(al[mt], sA + aoff[mt] + (((ch + 4) ^ swz) << 4));
            }
            #pragma unroll
            for (int np = 0; np < 2; np++) {
                uint32_t r[4];
                LDSM4(r, sB + boff[np] + ((ch ^ swz) << 4));
                bh[2 * np][0] = r[0]; bh[2 * np + 1][0] = r[1];
                bh[2 * np][1] = r[2]; bh[2 * np + 1][1] = r[3];
                LDSM4(r, sB + boff[np] + (((ch + 4) ^ swz) << 4));
                bl[2 * np][0] = r[0]; bl[2 * np + 1][0] = r[1];
                bl[2 * np][1] = r[2]; bl[2 * np + 1][1] = r[3];
            }
            #pragma unroll
            for (int mt = 0; mt < 4; mt++)
                #pragma unroll
                for (int nt = 0; nt < 4; nt++) {
                    MMA16816(acc[mt][nt], ah[mt], bh[nt]);
                    MMA16816(acc[mt][nt], ah[mt], bl[nt]);
                    MMA16816(acc[mt][nt], al[mt], bh[nt]);
                }
        }
        __syncthreads();
    }

    // epilogue
    const bool doadd = (gridDim.z > 1);
    const int mrow = lane >> 2, ncol = (lane & 3) << 1;
    #pragma unroll
    for (int mt = 0; mt < 4; mt++) {
        #pragma unroll
        for (int nt = 0; nt < 4; nt++) {
            const int n = n0 + wn * 32 + nt * 8 + ncol;
            if (n >= nvalid) continue;
            float* base;
            int nn;
            if (n < split) { base = out0; nn = n;         }
            else           { base = out1; nn = n - split; }
            const int ld = (n < split) ? ld0 : ld1;
            const int m1 = m0 + wm * 64 + mt * 16 + mrow;
            const int m2 = m1 + 8;
            if (doadd) {
                if (m1 < M)
                    asm volatile("red.global.add.v2.f32 [%0], {%1,%2};"
                                 :: "l"(base + (size_t)m1 * ld + nn),
                                    "f"(acc[mt][nt][0]), "f"(acc[mt][nt][1]) : "memory");
                if (m2 < M)
                    asm volatile("red.global.add.v2.f32 [%0], {%1,%2};"
                                 :: "l"(base + (size_t)m2 * ld + nn),
                                    "f"(acc[mt][nt][2]), "f"(acc[mt][nt][3]) : "memory");
            } else {
                if (m1 < M)
                    *(float2*)(base + (size_t)m1 * ld + nn) =
                        make_float2(acc[mt][nt][0], acc[mt][nt][1]);
                if (m2 < M)
                    *(float2*)(base + (size_t)m2 * ld + nn) =
                        make_float2(acc[mt][nt][2], acc[mt][nt][3]);
            }
        }
    }
}

// ---------------------------------------------------------------------------
// Attention coefficients, warp per (n,head), C=256, H=4
// ---------------------------------------------------------------------------
__global__ void attn_warp_kernel(const float* __restrict__ h,
                                 const float* __restrict__ a_s,
                                 const float* __restrict__ a_d,
                                 float* __restrict__ als, float* __restrict__ ald) {
    const int w = (blockIdx.x * blockDim.x + threadIdx.x) >> 5;
    if (w >= NN * 4) return;
    const int lane = threadIdx.x & 31;
    const int hh = w & 3;
    const float4* row = (const float4*)(h + (size_t)w * 256);
    const float4* as = (const float4*)(a_s + hh * 256);
    const float4* ad = (const float4*)(a_d + hh * 256);
    float s1 = 0.f, s2 = 0.f;
    #pragma unroll
    for (int i = 0; i < 2; i++) {
        const float4 v = row[lane + i * 32];
        const float4 a = as[lane + i * 32];
        const float4 b = ad[lane + i * 32];
        s1 += v.x * a.x + v.y * a.y + v.z * a.z + v.w * a.w;
        s2 += v.x * b.x + v.y * b.y + v.z * b.z + v.w * b.w;
    }
    #pragma unroll
    for (int o = 16; o; o >>= 1) {
        s1 += __shfl_xor_sync(0xffffffffu, s1, o);
        s2 += __shfl_xor_sync(0xffffffffu, s2, o);
    }
    if (lane == 0) { als[w] = s1; ald[w] = s2; }
}

// Layer 3 attention coefficients (H=6, C=6)
__global__ void attn_coeff3_kernel(const float* __restrict__ h,
                                   const float* __restrict__ a_s,
                                   const float* __restrict__ a_d,
                                   float* __restrict__ als, float* __restrict__ ald) {
    const int idx = blockIdx.x * blockDim.x + threadIdx.x;
    if (idx >= NN * 6) return;
    const int hh = idx % 6;
    const float* row = h + (size_t)idx * 6;
    const float* as = a_s + hh * 6;
    const float* ad = a_d + hh * 6;
    float s1 = 0.f, s2 = 0.f;
    #pragma unroll
    for (int c = 0; c < 6; c++) {
        const float v = row[c];
        s1 += v * as[c];
        s2 += v * ad[c];
    }
    als[idx] = s1;
    ald[idx] = s2;
}

// ---------------------------------------------------------------------------
// Fused CSR aggregation + epilogue for layers 1-2 (H=4, C=256):
// out = elu(sum_e alpha_e h[src_e] + b + lin + bl) -> bf16 hi/lo for next GEMM
// One block (256 thr) per dst; softmax without max-shift (logits O(1)).
// ---------------------------------------------------------------------------
__global__ __launch_bounds__(256)
void aggr_fused_kernel(const int* __restrict__ rowptr, const int* __restrict__ csr,
                       const float* __restrict__ h,
                       const float* __restrict__ als, const float* __restrict__ ald,
                       const float* __restrict__ b, const float* __restrict__ lin,
                       const float* __restrict__ bl,
                       __nv_bfloat16* __restrict__ oh, __nv_bfloat16* __restrict__ ol) {
    __shared__ float s_ex[DCAP * 4];
    __shared__ int   s_src[DCAP];
    __shared__ float s_sum[4];
    const int dst = blockIdx.x;
    const int rs = rowptr[dst], re = rowptr[dst + 1];
    const int deg = re - rs;
    const int tid = threadIdx.x;
    if (tid < 4) s_sum[tid] = 0.f;
    __syncthreads();

    // Phase A: exp(leaky(logit)) per (edge, head) + denominator
    for (int idx = tid; idx < deg * 4; idx += 256) {
        const int e = idx >> 2, hh = idx & 3;
        const int src = csr[rs + e];
        if (hh == 0 && e < DCAP) s_src[e] = src;
        float v = als[src * 4 + hh] + ald[dst * 4 + hh];
        v = v > 0.f ? v : NEG * v;
        const float ex = __expf(v);
        if (e < DCAP) s_ex[e * 4 + hh] = ex;
        atomicAdd(&s_sum[hh], ex);
    }
    __syncthreads();

    // Phase B: weighted gather; thread owns 4 channels (same head)
    const int head = tid >> 6;
    const float isum = 1.f / (s_sum[head] + 1e-16f);
    float4 acc = make_float4(0.f, 0.f, 0.f, 0.f);
    for (int e = 0; e < deg; e++) {
        int src; float ex;
        if (e < DCAP) { src = s_src[e]; ex = s_ex[e * 4 + head]; }
        else {
            src = csr[rs + e];
            float v = als[src * 4 + head] + ald[dst * 4 + head];
            v = v > 0.f ? v : NEG * v;
            ex = __expf(v);
        }
        const float a = ex * isum;
        const float4 hv = *(const float4*)(h + (size_t)src * HID + tid * 4);
        acc.x += a * hv.x; acc.y += a * hv.y; acc.z += a * hv.z; acc.w += a * hv.w;
    }

    // Epilogue: + b + lin + bl, ELU, split to bf16 hi/lo
    const float4 lv  = *(const float4*)(lin + (size_t)dst * HID + tid * 4);
    const float4 b4  = *(const float4*)(b + tid * 4);
    const float4 bl4 = *(const float4*)(bl + tid * 4);
    float vals[4] = { acc.x + lv.x + b4.x + bl4.x, acc.y + lv.y + b4.y + bl4.y,
                      acc.z + lv.z + b4.z + bl4.z, acc.w + lv.w + b4.w + bl4.w };
    __nv_bfloat16 hi[4], lo[4];
    #pragma unroll
    for (int j = 0; j < 4; j++) {
        const float v = vals[j] > 0.f ? vals[j] : expm1f(vals[j]);
        hi[j] = __float2bfloat16(v);
        lo[j] = __float2bfloat16(v - __bfloat162float(hi[j]));
    }
    *(uint2*)(oh + (size_t)dst * HID + tid * 4) = *(uint2*)hi;
    *(uint2*)(ol + (size_t)dst * HID + tid * 4) = *(uint2*)lo;
}

// ---------------------------------------------------------------------------
// Fused layer-3 aggregation + head-mean + biases + residual + log_softmax.
// One block (64 thr) per dst.
// ---------------------------------------------------------------------------
__global__ __launch_bounds__(64)
void aggr3_fused_kernel(const int* __restrict__ rowptr, const int* __restrict__ csr,
                        const float* __restrict__ h3,
                        const float* __restrict__ als, const float* __restrict__ ald,
                        const float* __restrict__ b3, const float* __restrict__ lin3,
                        const float* __restrict__ bl3,
                        float* __restrict__ out) {
    __shared__ float s_ex[DCAP3 * 6];
    __shared__ int   s_src[DCAP3];
    __shared__ float s_sum[6];
    __shared__ float s_val[36];
    __shared__ float s_lg[6];
    const int dst = blockIdx.x;
    const int rs = rowptr[dst], re = rowptr[dst + 1];
    const int deg = re - rs;
    const int tid = threadIdx.x;
    if (tid < 6) s_sum[tid] = 0.f;
    __syncthreads();

    for (int idx = tid; idx < deg * 6; idx += 64) {
        const int e = idx / 6, hh = idx - e * 6;
        const int src = csr[rs + e];
        if (hh == 0 && e < DCAP3) s_src[e] = src;
        float v = als[src * 6 + hh] + ald[dst * 6 + hh];
        v = v > 0.f ? v : NEG * v;
        const float ex = __expf(v);
        if (e < DCAP3) s_ex[e * 6 + hh] = ex;
        atomicAdd(&s_sum[hh], ex);
    }
    __syncthreads();

    if (tid < 36) {
        const int c = tid;
        const int head = c / 6;
        const float isum = 1.f / (s_sum[head] + 1e-16f);
        float acc = 0.f;
        for (int e = 0; e < deg; e++) {
            int src; float ex;
            if (e < DCAP3) { src = s_src[e]; ex = s_ex[e * 6 + head]; }
            else {
                src = csr[rs + e];
                float v = als[src * 6 + head] + ald[dst * 6 + head];
                v = v > 0.f ? v : NEG * v;
                ex = __expf(v);
            }
            acc += ex * isum * h3[(size_t)src * 36 + c];
        }
        s_val[c] = acc;
    }
    __syncthreads();

    if (tid < 6) {
        const int c = tid;
        float m = 0.f;
        #pragma unroll
        for (int hh = 0; hh < 6; hh++) m += s_val[hh * 6 + c];
        s_lg[c] = m * (1.f / 6.f) + b3[c] + lin3[dst * 6 + c] + bl3[c];
    }
    __syncthreads();
    if (tid < 6) {
        float mx = s_lg[0];
        #pragma unroll
        for (int c = 1; c < 6; c++) mx = fmaxf(mx, s_lg[c]);
        float se = 0.f;
        #pragma unroll
        for (int c = 0; c < 6; c++) se += expf(s_lg[c] - mx);
        const float lse = logf(se) + mx;
        out[dst * 6 + tid] = s_lg[tid] - lse;
    }
}

// ---------------------------------------------------------------------------
// Host launcher
// ---------------------------------------------------------------------------
extern "C" void kernel_launch(void* const* d_in, const int* in_sizes, int n_in,
                              void* d_out, int out_size) {
    const float* x0  = (const float*)d_in[0];
    const void*  ei  = d_in[1];
    const float* W1  = (const float*)d_in[2];
    const float* as1 = (const float*)d_in[3];
    const float* ad1 = (const float*)d_in[4];
    const float* b1  = (const float*)d_in[5];
    const float* Wl1 = (const float*)d_in[6];
    const float* bl1 = (const float*)d_in[7];
    const float* W2  = (const float*)d_in[8];
    const float* as2 = (const float*)d_in[9];
    const float* ad2 = (const float*)d_in[10];
    const float* b2  = (const float*)d_in[11];
    const float* Wl2 = (const float*)d_in[12];
    const float* bl2 = (const float*)d_in[13];
    const float* W3  = (const float*)d_in[14];
    const float* as3 = (const float*)d_in[15];
    const float* ad3 = (const float*)d_in[16];
    const float* b3  = (const float*)d_in[17];
    const float* Wl3 = (const float*)d_in[18];
    const float* bl3 = (const float*)d_in[19];
    float* out = (float*)d_out;

    float *h, *lin, *als, *ald, *h3, *lin3;
    __nv_bfloat16 *Axh, *Axl, *Bth, *Btl;
    int *deg, *cnt, *rowptr, *csr;
    cudaGetSymbolAddress((void**)&h,    g_h);
    cudaGetSymbolAddress((void**)&lin,  g_lin);
    cudaGetSymbolAddress((void**)&als,  g_als);
    cudaGetSymbolAddress((void**)&ald,  g_ald);
    cudaGetSymbolAddress((void**)&h3,   g_h3);
    cudaGetSymbolAddress((void**)&lin3, g_lin3);
    cudaGetSymbolAddress((void**)&Axh,  g_Axh);
    cudaGetSymbolAddress((void**)&Axl,  g_Axl);
    cudaGetSymbolAddress((void**)&Bth,  g_Bth);
    cudaGetSymbolAddress((void**)&Btl,  g_Btl);
    cudaGetSymbolAddress((void**)&deg,  g_deg);
    cudaGetSymbolAddress((void**)&cnt,  g_cnt);
    cudaGetSymbolAddress((void**)&rowptr, g_rowptr);
    cudaGetSymbolAddress((void**)&csr,  g_csr);

    const int SMEMB = 98304;   // 3 stages x 32KB
    cudaFuncSetAttribute(hmma_gemm_kernel,
                         cudaFuncAttributeMaxDynamicSharedMemorySize, SMEMB);

    const dim3 cbT(32, 8);
    const int egrid = (ET + 255) / 256;

    // ---- Graph preprocessing (shared by all 3 layers) ----
    detect_kernel<<<1, 1>>>((const unsigned int*)ei);
    zero_csr_kernel<<<(NN + 255) / 256, 256>>>(deg, cnt);
    count_kernel<<<egrid, 256>>>(ei, deg);
    scan_kernel<<<1, 1024>>>(deg, rowptr);
    scatter_kernel<<<egrid, 256>>>(ei, rowptr, cnt, csr);

    // ---- Layer 1 (K=512, fused N = 1024 | 1024) ----
    convB_kernel<<<dim3(32, 16), cbT>>>(W1,  512, 1024, Bth, Btl, 0,    512);
    convB_kernel<<<dim3(32, 16), cbT>>>(Wl1, 512, 1024, Bth, Btl, 1024, 512);
    convA_kernel<<<(NN * 512 / 4 + 255) / 256, 256>>>(x0, Axh, Axl, NN * 512 / 4);
    hmma_gemm_kernel<<<dim3(16, 79, 1), 256, SMEMB>>>(Axh, Axl, Bth, Btl,
        NN, 512, h, 1024, 1024, lin, 1024, 2048);
    attn_warp_kernel<<<5000, 256>>>(h, as1, ad1, als, ald);
    aggr_fused_kernel<<<NN, 256>>>(rowptr, csr, h, als, ald, b1, lin, bl1, Axh, Axl);

    // ---- Layer 2 (K=1024) ----
    convB_kernel<<<dim3(32, 32), cbT>>>(W2,  1024, 1024, Bth, Btl, 0,    1024);
    convB_kernel<<<dim3(32, 32), cbT>>>(Wl2, 1024, 1024, Bth, Btl, 1024, 1024);
    hmma_gemm_kernel<<<dim3(16, 79, 1), 256, SMEMB>>>(Axh, Axl, Bth, Btl,
        NN, 1024, h, 1024, 1024, lin, 1024, 2048);
    attn_warp_kernel<<<5000, 256>>>(h, as2, ad2, als, ald);
    aggr_fused_kernel<<<NN, 256>>>(rowptr, csr, h, als, ald, b2, lin, bl2, Axh, Axl);

    // ---- Layer 3 (K=1024, N tile=128 zero-padded, split-K=4) ----
    zero_bf16_kernel<<<(128 * 1024 + 255) / 256, 256>>>(Bth, Btl, 128 * 1024);
    convB_kernel<<<dim3(2, 32), cbT>>>(W3,  1024, 36, Bth, Btl, 0,  1024);
    convB_kernel<<<dim3(1, 32), cbT>>>(Wl3, 1024, 6,  Bth, Btl, 36, 1024);
    zero_f32_kernel<<<(NN * 36 + 255) / 256, 256>>>(h3, NN * 36, lin3, NN * 6);
    hmma_gemm_kernel<<<dim3(1, 79, 4), 256, SMEMB>>>(Axh, Axl, Bth, Btl,
        NN, 1024, h3, 36, 36, lin3, 6, 42);
    attn_coeff3_kernel<<<(NN * 6 + 255) / 256, 256>>>(h3, as3, ad3, als, ald);
    aggr3_fused_kernel<<<NN, 64>>>(rowptr, csr, h3, als, ald, b3, lin3, bl3, out);
}